// round 13
// baseline (speedup 1.0000x reference)
#include <cuda_runtime.h>

// Fixed problem shapes
#define BB 16
#define TT 288
#define NN 4096
#define HH 10
#define RR 16
#define TCIN 8                      // t-chunks INSIDE a k1 block
#define TPC (TT / TCIN)             // 36
#define X1 64                       // k1 n-groups (32 float4 cols each)
#define NBLKS1 (X1 * BB)            // 1024 k1 blocks
#define PXB 16                      // pred blocks per b in epilogue

// Scratch (fully rewritten each replay before reads; NO counters/flags).
__device__ float4 g_fin[BB][NN / 2];   // FINAL (s0,c0,s1,c1) per node pair: 512KB
__device__ float2 g_blk[NBLKS1];       // per-k1-block (sum, cnt): 8KB

// ---------------------------------------------------------------------------
// Kernel 1: heavy streaming pass over 151MB, T-reduction completed in-block.
// grid (64,16) = 1024 blocks x 256 thr. Triggers programmatic launch of the
// epilogue as each block completes.
// ---------------------------------------------------------------------------
__global__ void __launch_bounds__(256) k1_main(const float4* __restrict__ data) {
    const int tid  = threadIdx.x;
    const int col  = tid & 31;
    const int tc   = tid >> 5;            // 0..7
    const int x    = blockIdx.x;
    const int b    = blockIdx.y;
    const int colg = x * 32 + col;        // global float4 column [0, 2048)

    const float4* __restrict__ p =
        data + (size_t)(b * TT + tc * TPC) * (NN / 2) + colg;

    float s0 = 0.f, s1 = 0.f, c0 = 0.f, c1 = 0.f;
    #pragma unroll 6
    for (int t = 0; t < TPC; ++t) {
        float4 v = __ldcs(p);
        p += NN / 2;
        if (v.x != -1.0f) { s0 += v.x; c0 += 1.0f; }
        if (v.z != -1.0f) { s1 += v.z; c1 += 1.0f; }
    }

    __shared__ float4 sh[TCIN][32];
    sh[tc][col] = make_float4(s0, c0, s1, c1);
    __syncthreads();

    if (tid < 32) {
        float4 a = sh[0][tid];
        float fs0 = a.x, fc0 = a.y, fs1 = a.z, fc1 = a.w;
        #pragma unroll
        for (int k = 1; k < TCIN; ++k) {
            float4 v = sh[k][tid];
            fs0 += v.x; fc0 += v.y; fs1 += v.z; fc1 += v.w;
        }
        g_fin[b][x * 32 + tid] = make_float4(fs0, fc0, fs1, fc1);

        float s = fs0 + fs1;
        float c = fc0 + fc1;
        #pragma unroll
        for (int o = 16; o > 0; o >>= 1) {
            s += __shfl_down_sync(0xffffffffu, s, o);
            c += __shfl_down_sync(0xffffffffu, c, o);
        }
        if (tid == 0)
            g_blk[b * X1 + x] = make_float2(s, c);
    }

    // Allow the epilogue grid to launch as soon as all k1 blocks reach here.
    cudaTriggerProgrammaticLaunchCompletion();
}

// ---------------------------------------------------------------------------
// Kernel 2 (epilogue): grid (PXB+1, BB) = 272 independent blocks x 256 thr.
// Launched with programmatic stream serialization: blocks become resident and
// run their k1-independent preamble (cid loads, index math) during k1's tail;
// cudaGridDependencySynchronize() provides the data edge.
//   x < 16 : pred_speed — 128 float4 cols, 2 threads/col (5 stores each)
//   x == 16: regional for batch b — cid preloaded, warp-split smem atomics
// ---------------------------------------------------------------------------
__global__ void __launch_bounds__(256) k2_epilogue(const int* __restrict__ cid,
                                                   float* __restrict__ out) {
    const int tid = threadIdx.x;
    const int b   = blockIdx.y;
    const int x   = blockIdx.x;
    const int wid = tid >> 5, lane = tid & 31;
    const bool isReg = (x == PXB);

    // ---- preamble: independent of k1 ----
    int2 cc[8];
    if (isReg) {
        #pragma unroll
        for (int k = 0; k < 8; ++k)
            cc[k] = ((const int2*)cid)[k * 256 + tid];
    }
    const int q  = x * 128 + (tid & 127);   // pred: float4 column
    const int hg = tid >> 7;                // pred: h-half (0 or 1)

    // ---- wait for k1's memory ----
    cudaGridDependencySynchronize();

    // ---- issue the dependent load ASAP (overlaps gmean reduce) ----
    float4 f;
    if (!isReg) f = g_fin[b][q];

    // ---- gmean reduce over 8KB g_blk (every block; storm-free at 272) ----
    float s = 0.f, c = 0.f;
    #pragma unroll
    for (int i = tid; i < NBLKS1; i += 256) {
        float2 v = g_blk[i];
        s += v.x; c += v.y;
    }
    #pragma unroll
    for (int o = 16; o > 0; o >>= 1) {
        s += __shfl_down_sync(0xffffffffu, s, o);
        c += __shfl_down_sync(0xffffffffu, c, o);
    }
    __shared__ float sh_s[8], sh_c[8];
    __shared__ float sh_gm;
    if (lane == 0) { sh_s[wid] = s; sh_c[wid] = c; }
    __syncthreads();
    if (tid == 0) {
        s = 0.f; c = 0.f;
        #pragma unroll
        for (int w = 0; w < 8; ++w) { s += sh_s[w]; c += sh_c[w]; }
        sh_gm = s / fmaxf(c, 1.0f);
    }
    __syncthreads();
    const float gm   = sh_gm;
    const float invT = 1.0f / (float)TT;

    if (!isReg) {
        // ---- pred_speed: 5 float2 stores per thread ----
        const float m0 = (f.x + ((float)TT - f.y) * gm) * invT;
        const float m1 = (f.z + ((float)TT - f.w) * gm) * invT;
        const float2 mm = make_float2(m0, m1);

        float2* __restrict__ o2 = (float2*)out;
        const int h0 = hg * 5;
        #pragma unroll
        for (int j = 0; j < 5; ++j)
            o2[((size_t)b * HH + h0 + j) * (NN / 2) + q] = mm;
        return;
    }

    // ---- regional for batch b ----
    __shared__ float rs[8][RR];
    __shared__ float rc[8][RR];
    if (lane < RR) { rs[wid][lane] = 0.f; rc[wid][lane] = 0.f; }
    __syncthreads();

    #pragma unroll
    for (int k = 0; k < 8; ++k) {
        const float4 fr = g_fin[b][k * 256 + tid];
        const float m0 = (fr.x + ((float)TT - fr.y) * gm) * invT;
        const float m1 = (fr.z + ((float)TT - fr.w) * gm) * invT;
        atomicAdd(&rs[wid][cc[k].x], m0);
        atomicAdd(&rc[wid][cc[k].x], 1.0f);
        atomicAdd(&rs[wid][cc[k].y], m1);
        atomicAdd(&rc[wid][cc[k].y], 1.0f);
    }
    __syncthreads();

    if (tid < RR) {
        float a = 0.f, n = 0.f;
        #pragma unroll
        for (int w = 0; w < 8; ++w) { a += rs[w][tid]; n += rc[w][tid]; }
        const float val = a / fmaxf(n, 1.0f);

        float* __restrict__ ro = out + (size_t)BB * HH * NN;
        #pragma unroll
        for (int h = 0; h < HH; ++h)
            ro[((size_t)b * HH + h) * RR + tid] = val;
    }
}

// ---------------------------------------------------------------------------
extern "C" void kernel_launch(void* const* d_in, const int* in_sizes, int n_in,
                              void* d_out, int out_size) {
    const float4* data = (const float4*)d_in[0];
    const int*    cid  = (const int*)d_in[1];
    float*        out  = (float*)d_out;

    dim3 g1(X1, BB);          // (64,16) = 1024 blocks
    k1_main<<<g1, 256>>>(data);

    // Epilogue with programmatic dependent launch (overlaps k1's tail drain).
    cudaLaunchConfig_t cfg = {};
    cfg.gridDim  = dim3(PXB + 1, BB);   // (17,16) = 272 blocks
    cfg.blockDim = dim3(256);
    cfg.dynamicSmemBytes = 0;
    cfg.stream   = 0;
    cudaLaunchAttribute attrs[1];
    attrs[0].id = cudaLaunchAttributeProgrammaticStreamSerialization;
    attrs[0].val.programmaticStreamSerializationAllowed = 1;
    cfg.attrs    = attrs;
    cfg.numAttrs = 1;
    cudaLaunchKernelEx(&cfg, k2_epilogue, cid, out);
}